// round 5
// baseline (speedup 1.0000x reference)
#include <cuda_runtime.h>
#include <cstdint>
#include <cstddef>

#define BATCH 256
#define TSEQ  512
#define IDIM  64
#define HDIM  512
#define ODIM  512
#define CLUSTER_N 8
#define NCLUSTERS 16          // BATCH / BTILE
#define BTILE 16
#define STEP_THREADS 128

typedef unsigned long long ull;

// ---- scratch (static device allocations only) ----
__device__ float g_xp[(size_t)TSEQ * BATCH * HDIM];   // [t][b][h], 256 MiB
__device__ float g_hlast[(size_t)BATCH * HDIM];       // final h, [b][j]

// ---- packed f32x2 helpers ----
__device__ __forceinline__ ull pk2(float lo, float hi) {
    ull r; asm("mov.b64 %0, {%1,%2};" : "=l"(r) : "f"(lo), "f"(hi)); return r;
}
__device__ __forceinline__ float2 upk2(ull v) {
    float2 r; asm("mov.b64 {%0,%1}, %2;" : "=f"(r.x), "=f"(r.y) : "l"(v)); return r;
}
__device__ __forceinline__ ull fma2(ull a, ull b, ull c) {
    ull d; asm("fma.rn.f32x2 %0, %1, %2, %3;" : "=l"(d) : "l"(a), "l"(b), "l"(c)); return d;
}

// ---- SMEM layout (dynamic), per CTA ----
// ws     : [512 k][64 j] float                = 131072 B
// shard  : [2 par][64 j][16 b] float          =   8192 B   (this CTA's computed h slice)
// hstage : [2 buf][128 k][36 float] (16 b splatted float2 + 4 pad) = 36864 B
#define WS_BYTES     131072
#define SHARD_BYTES  8192
#define HROW         36                      // floats per hstage row (pad for banks)
#define HSTAGE_BUF   (128 * HROW)            // floats per buffer
#define SMEM_TOTAL   (WS_BYTES + SHARD_BYTES + 2 * HSTAGE_BUF * 4)

// ============================================================================
// Kernel A: xp[t][b][:] = x[b][t][:] @ Whx + bh.  8 rows (same b) per CTA.
// ============================================================================
__global__ void __launch_bounds__(128) xproj_kernel(
    const float* __restrict__ x, const float* __restrict__ Whx,
    const float* __restrict__ bh)
{
    __shared__ float xs[8][IDIM];
    int row0 = blockIdx.x * 8;
    int b = row0 >> 9, t0 = row0 & (TSEQ - 1);
    int tid = threadIdx.x;
    for (int i = tid; i < 8 * IDIM; i += 128)
        xs[i >> 6][i & 63] = x[(size_t)(row0 + (i >> 6)) * IDIM + (i & 63)];
    __syncthreads();

    int j0 = tid * 4;
    ull a[8][2] = {};
    #pragma unroll 4
    for (int k = 0; k < IDIM; k++) {
        float4 w = *reinterpret_cast<const float4*>(Whx + (size_t)k * HDIM + j0);
        ull w01 = pk2(w.x, w.y), w23 = pk2(w.z, w.w);
        #pragma unroll
        for (int r = 0; r < 8; r++) {
            float xv = xs[r][k];
            ull x2 = pk2(xv, xv);
            a[r][0] = fma2(w01, x2, a[r][0]);
            a[r][1] = fma2(w23, x2, a[r][1]);
        }
    }
    float4 bv = *reinterpret_cast<const float4*>(bh + j0);
    #pragma unroll
    for (int r = 0; r < 8; r++) {
        float2 p0 = upk2(a[r][0]), p1 = upk2(a[r][1]);
        float4 o;
        o.x = p0.x + bv.x; o.y = p0.y + bv.y;
        o.z = p1.x + bv.z; o.w = p1.y + bv.w;
        *reinterpret_cast<float4*>(
            g_xp + ((size_t)(t0 + r) * BATCH + b) * HDIM + j0) = o;
    }
}

// ============================================================================
// Kernel B: cluster-local persistent recurrence.
// Grid 128 CTAs, cluster (8,1,1): cluster c = batch rows [16c,16c+16),
// rank r = j-columns [64r, 64r+64). Whh slice local SMEM (128 KB).
// h shards exchanged via DSMEM; sync = barrier.cluster per step.
// Warp tile: wj = wrp&1 (32 j), wb = wrp>>1 (8 b). Thread: 4j x 2b.
// Inner kl: LDS.128 W {j-pairs} + LDS.128 h-splat {b0b0,b1b1} + 4 FFMA2.
// ============================================================================
__global__ void __launch_bounds__(STEP_THREADS, 1) __cluster_dims__(CLUSTER_N, 1, 1)
rnn_persistent(const float* __restrict__ Whh)
{
    extern __shared__ char sm[];
    float* ws     = reinterpret_cast<float*>(sm);
    float* shard  = reinterpret_cast<float*>(sm + WS_BYTES);
    float* hstage = reinterpret_cast<float*>(sm + WS_BYTES + SHARD_BYTES);

    uint32_t rank; asm("mov.u32 %0, %%cluster_ctarank;" : "=r"(rank));
    const int cid = blockIdx.x / CLUSTER_N;
    const int tid = threadIdx.x;
    const int lane = tid & 31, wrp = tid >> 5;
    const int wj = wrp & 1, wb = wrp >> 1;
    const int jg = lane & 7, bg = lane >> 3;
    const int jl0 = wj * 32 + jg * 4;         // local j quad base (0..60)
    const int bl0 = wb * 8 + bg * 2;          // local b pair base (0..14)
    const int j0g = (int)rank * 64 + jl0;     // global j
    const int b0g = cid * BTILE + bl0;        // global b

    // ---- load Whh slice [512][rank*64 .. +64) into SMEM (once) ----
    for (int i = tid; i < 512 * 16; i += STEP_THREADS) {   // 8192 float4s
        int k = i >> 4, q = (i & 15) * 4;
        *reinterpret_cast<float4*>(ws + (size_t)k * 64 + q) =
            *reinterpret_cast<const float4*>(Whh + (size_t)k * HDIM + rank * 64 + q);
    }
    __syncthreads();

    // ---- peer shard base addresses via mapa ----
    uint32_t shard_u32 = (uint32_t)__cvta_generic_to_shared(shard);
    uint32_t peer[CLUSTER_N];
    #pragma unroll
    for (int r = 0; r < CLUSTER_N; r++) {
        asm("mapa.shared::cluster.u32 %0, %1, %2;"
            : "=r"(peer[r]) : "r"(shard_u32), "r"(r));
    }

    for (int t = 0; t < TSEQ; t++) {
        const float* xpt = g_xp + (size_t)t * BATCH * HDIM;
        float4 xv0 = *reinterpret_cast<const float4*>(xpt + (size_t)b0g * HDIM + j0g);
        float4 xv1 = *reinterpret_cast<const float4*>(xpt + (size_t)(b0g + 1) * HDIM + j0g);
        ull a0 = 0ull, a1 = 0ull, a2 = 0ull, a3 = 0ull;

        if (t > 0) {
            asm volatile("barrier.cluster.wait.aligned;" ::: "memory");
            const int par = (t - 1) & 1;

            // ---- stage chunk 0 (DSMEM ld -> reg -> splat STS) ----
            float4 sreg[4];
            #pragma unroll
            for (int p = 0; p < 4; p++) {
                int i = p * 128 + tid;                 // 0..511 float4 of chunk 0
                int owner = i >> 8;                    // rank 0 or 1
                uint32_t src = (owner ? peer[1] : peer[0])
                             + (uint32_t)(par * 4096 + (i & 255) * 16);
                asm volatile("ld.shared::cluster.v4.f32 {%0,%1,%2,%3}, [%4];"
                             : "=f"(sreg[p].x), "=f"(sreg[p].y),
                               "=f"(sreg[p].z), "=f"(sreg[p].w) : "r"(src));
            }
            #pragma unroll
            for (int p = 0; p < 4; p++) {
                int i = p * 128 + tid;
                float* d = hstage + (size_t)(i >> 2) * HROW + (i & 3) * 8;
                *reinterpret_cast<float4*>(d) =
                    make_float4(sreg[p].x, sreg[p].x, sreg[p].y, sreg[p].y);
                *reinterpret_cast<float4*>(d + 4) =
                    make_float4(sreg[p].z, sreg[p].z, sreg[p].w, sreg[p].w);
            }
            __syncthreads();

            #pragma unroll
            for (int c = 0; c < 4; c++) {
                // prefetch chunk c+1 shards into regs (latency hides under compute)
                if (c < 3) {
                    #pragma unroll
                    for (int p = 0; p < 4; p++) {
                        int i = p * 128 + tid;
                        int owner = i >> 8;
                        uint32_t src = (owner ? peer[2 * (c + 1) + 1] : peer[2 * (c + 1)])
                                     + (uint32_t)(par * 4096 + (i & 255) * 16);
                        asm volatile("ld.shared::cluster.v4.f32 {%0,%1,%2,%3}, [%4];"
                                     : "=f"(sreg[p].x), "=f"(sreg[p].y),
                                       "=f"(sreg[p].z), "=f"(sreg[p].w) : "r"(src));
                    }
                }
                // compute chunk c
                const float* wkc = ws + (size_t)(c * 128) * 64 + jl0;
                const float* hsc = hstage + (size_t)(c & 1) * HSTAGE_BUF + bl0 * 2;
                #pragma unroll 8
                for (int kl = 0; kl < 128; kl++) {
                    ulonglong2 w2 = *reinterpret_cast<const ulonglong2*>(wkc + (size_t)kl * 64);
                    ulonglong2 h2 = *reinterpret_cast<const ulonglong2*>(hsc + (size_t)kl * HROW);
                    a0 = fma2(w2.x, h2.x, a0);
                    a1 = fma2(w2.y, h2.x, a1);
                    a2 = fma2(w2.x, h2.y, a2);
                    a3 = fma2(w2.y, h2.y, a3);
                }
                // store staged regs for chunk c+1, then make visible
                if (c < 3) {
                    float* hb = hstage + (size_t)((c + 1) & 1) * HSTAGE_BUF;
                    #pragma unroll
                    for (int p = 0; p < 4; p++) {
                        int i = p * 128 + tid;
                        float* d = hb + (size_t)(i >> 2) * HROW + (i & 3) * 8;
                        *reinterpret_cast<float4*>(d) =
                            make_float4(sreg[p].x, sreg[p].x, sreg[p].y, sreg[p].y);
                        *reinterpret_cast<float4*>(d + 4) =
                            make_float4(sreg[p].z, sreg[p].z, sreg[p].w, sreg[p].w);
                    }
                    __syncthreads();
                }
            }
        }

        // ---- epilogue: tanh(xp + acc), write own shard, arrive ----
        float2 p0 = upk2(a0), p1 = upk2(a1), p2 = upk2(a2), p3 = upk2(a3);
        float ob0[4] = { tanhf(xv0.x + p0.x), tanhf(xv0.y + p0.y),
                         tanhf(xv0.z + p1.x), tanhf(xv0.w + p1.y) };
        float ob1[4] = { tanhf(xv1.x + p2.x), tanhf(xv1.y + p2.y),
                         tanhf(xv1.z + p3.x), tanhf(xv1.w + p3.y) };
        float* sh = shard + (size_t)(t & 1) * 1024;   // [64][16]
        #pragma unroll
        for (int jj = 0; jj < 4; jj++)
            *reinterpret_cast<float2*>(sh + (size_t)(jl0 + jj) * 16 + bl0) =
                make_float2(ob0[jj], ob1[jj]);
        if (t == TSEQ - 1) {
            *reinterpret_cast<float4*>(g_hlast + (size_t)b0g * HDIM + j0g) =
                make_float4(ob0[0], ob0[1], ob0[2], ob0[3]);
            *reinterpret_cast<float4*>(g_hlast + (size_t)(b0g + 1) * HDIM + j0g) =
                make_float4(ob1[0], ob1[1], ob1[2], ob1[3]);
        }
        asm volatile("barrier.cluster.arrive.aligned;" ::: "memory");
    }
}

// ============================================================================
// Kernel C: out[b][:] = softmax(h_last[b][:] @ Wph + bo).
// ============================================================================
__global__ void __launch_bounds__(128) out_softmax_kernel(
    const float* __restrict__ Wph, const float* __restrict__ bo,
    float* __restrict__ out)
{
    __shared__ float hsr[HDIM];
    __shared__ float red[128];
    int b = blockIdx.x, tid = threadIdx.x;
    for (int k = tid; k < HDIM; k += 128)
        hsr[k] = g_hlast[(size_t)b * HDIM + k];
    __syncthreads();

    int j0 = tid * 4;
    ull a0 = 0ull, a1 = 0ull;
    #pragma unroll 8
    for (int k = 0; k < HDIM; k++) {
        float4 w = *reinterpret_cast<const float4*>(Wph + (size_t)k * ODIM + j0);
        ull hv = pk2(hsr[k], hsr[k]);
        a0 = fma2(pk2(w.x, w.y), hv, a0);
        a1 = fma2(pk2(w.z, w.w), hv, a1);
    }
    float4 bv = *reinterpret_cast<const float4*>(bo + j0);
    float2 p0 = upk2(a0), p1 = upk2(a1);
    float4 v;
    v.x = p0.x + bv.x; v.y = p0.y + bv.y;
    v.z = p1.x + bv.z; v.w = p1.y + bv.w;

    float m = fmaxf(fmaxf(v.x, v.y), fmaxf(v.z, v.w));
    red[tid] = m;
    __syncthreads();
    for (int s = 64; s > 0; s >>= 1) {
        if (tid < s) red[tid] = fmaxf(red[tid], red[tid + s]);
        __syncthreads();
    }
    m = red[0];
    __syncthreads();

    v.x = expf(v.x - m); v.y = expf(v.y - m);
    v.z = expf(v.z - m); v.w = expf(v.w - m);
    red[tid] = v.x + v.y + v.z + v.w;
    __syncthreads();
    for (int s = 64; s > 0; s >>= 1) {
        if (tid < s) red[tid] += red[tid + s];
        __syncthreads();
    }
    float inv = 1.0f / red[0];
    v.x *= inv; v.y *= inv; v.z *= inv; v.w *= inv;
    *reinterpret_cast<float4*>(out + (size_t)b * ODIM + j0) = v;
}

// ============================================================================
extern "C" void kernel_launch(void* const* d_in, const int* in_sizes, int n_in,
                              void* d_out, int out_size)
{
    const float* x   = (const float*)d_in[0];
    const float* Whx = (const float*)d_in[1];
    const float* Whh = (const float*)d_in[2];
    const float* bh  = (const float*)d_in[3];
    const float* Wph = (const float*)d_in[4];
    const float* bo  = (const float*)d_in[5];
    float* out = (float*)d_out;

    cudaFuncSetAttribute(rnn_persistent,
                         cudaFuncAttributeMaxDynamicSharedMemorySize, SMEM_TOTAL);

    xproj_kernel<<<BATCH * TSEQ / 8, 128>>>(x, Whx, bh);
    rnn_persistent<<<NCLUSTERS * CLUSTER_N, STEP_THREADS, SMEM_TOTAL>>>(Whh);
    out_softmax_kernel<<<BATCH, 128>>>(Wph, bo, out);
}

// round 7
// speedup vs baseline: 1.5290x; 1.5290x over previous
#include <cuda_runtime.h>
#include <cstdint>
#include <cstddef>

#define BATCH 256
#define TSEQ  512
#define IDIM  64
#define HDIM  512
#define ODIM  512
#define JCTAS   8            // j-partition: CTA r owns j in [64r, 64r+64)
#define BGROUPS 16           // batch groups of 16 rows
#define STEP_THREADS 128

typedef unsigned long long ull;

// ---- scratch (static device allocations only) ----
__device__ float  g_xp[(size_t)TSEQ * BATCH * HDIM];    // [t][b][h], 256 MiB
// hidden state, transposed + splatted: g_ht2[par][j][b] = {v,v}
__device__ float2 g_ht2[2][(size_t)HDIM * BATCH];       // 2 MiB
__device__ float  g_hlast[(size_t)BATCH * HDIM];        // final h, [b][j]
// per-CTA step flags, one 128B line each: flag[(g*8 + r)*32]
__device__ unsigned g_flags[JCTAS * BGROUPS * 32];

// ---- packed f32x2 helpers ----
__device__ __forceinline__ ull pk2(float lo, float hi) {
    ull r; asm("mov.b64 %0, {%1,%2};" : "=l"(r) : "f"(lo), "f"(hi)); return r;
}
__device__ __forceinline__ float2 upk2(ull v) {
    float2 r; asm("mov.b64 {%0,%1}, %2;" : "=f"(r.x), "=f"(r.y) : "l"(v)); return r;
}
__device__ __forceinline__ ull fma2(ull a, ull b, ull c) {
    ull d; asm("fma.rn.f32x2 %0, %1, %2, %3;" : "=l"(d) : "l"(a), "l"(b), "l"(c)); return d;
}

// ---- smem layout ----
#define WS_BYTES   131072                 // Whh slice [512][64] floats
#define HCHUNK_B   16384                  // one staged chunk: [128 k][16 b] float2
#define SMEM_TOTAL (WS_BYTES + 4 * HCHUNK_B)   // 192 KB

// ============================================================================
// Kernel 0: zero the flags (runs before rnn_persistent every replay).
// ============================================================================
__global__ void init_flags_kernel() {
    for (int i = threadIdx.x; i < JCTAS * BGROUPS * 32; i += blockDim.x)
        g_flags[i] = 0u;
}

// ============================================================================
// Kernel A: xp[t][b][:] = x[b][t][:] @ Whx + bh.  8 rows (same b) per CTA.
// ============================================================================
__global__ void __launch_bounds__(128) xproj_kernel(
    const float* __restrict__ x, const float* __restrict__ Whx,
    const float* __restrict__ bh)
{
    __shared__ float xs[8][IDIM];
    int row0 = blockIdx.x * 8;
    int b = row0 >> 9, t0 = row0 & (TSEQ - 1);
    int tid = threadIdx.x;
    for (int i = tid; i < 8 * IDIM; i += 128)
        xs[i >> 6][i & 63] = x[(size_t)(row0 + (i >> 6)) * IDIM + (i & 63)];
    __syncthreads();

    int j0 = tid * 4;
    ull a[8][2] = {};
    #pragma unroll 4
    for (int k = 0; k < IDIM; k++) {
        float4 w = *reinterpret_cast<const float4*>(Whx + (size_t)k * HDIM + j0);
        ull w01 = pk2(w.x, w.y), w23 = pk2(w.z, w.w);
        #pragma unroll
        for (int r = 0; r < 8; r++) {
            float xv = xs[r][k];
            ull x2 = pk2(xv, xv);
            a[r][0] = fma2(w01, x2, a[r][0]);
            a[r][1] = fma2(w23, x2, a[r][1]);
        }
    }
    float4 bv = *reinterpret_cast<const float4*>(bh + j0);
    #pragma unroll
    for (int r = 0; r < 8; r++) {
        float2 p0 = upk2(a[r][0]), p1 = upk2(a[r][1]);
        float4 o;
        o.x = p0.x + bv.x; o.y = p0.y + bv.y;
        o.z = p1.x + bv.z; o.w = p1.y + bv.w;
        *reinterpret_cast<float4*>(
            g_xp + ((size_t)(t0 + r) * BATCH + b) * HDIM + j0) = o;
    }
}

// ============================================================================
// Kernel B: persistent recurrence, flag-synced (no atomics).
// Grid (8 j, 16 b) = 128 CTAs x 128 thr, single wave (192KB smem -> 1 CTA/SM).
// CTA (r,g): j in [64r,64r+64), b in [16g,16g+16). Whh slice SMEM-resident.
// Per step: for each 128-k chunk wait on its 2 producer flags (tid0 poll +
// __syncthreads), cp.async.cg the 16KB chunk, compute (6 issue slots/kl),
// tanh epilogue, splat-store h, release own flag.
// ============================================================================
__global__ void __launch_bounds__(STEP_THREADS, 1) rnn_persistent(
    const float* __restrict__ Whh)
{
    extern __shared__ char sm[];
    float* ws = reinterpret_cast<float*>(sm);                    // [512][64]
    char*  hs = sm + WS_BYTES;                                   // 4 x 16KB
    uint32_t hs_u32 = (uint32_t)__cvta_generic_to_shared(hs);

    const int r = blockIdx.x;          // 0..7  (j slice)
    const int g = blockIdx.y;          // 0..15 (batch group)
    const int tid = threadIdx.x;
    const int lane = tid & 31, wrp = tid >> 5;
    const int wj = wrp & 1, wb = wrp >> 1;
    const int jg = lane & 7, bg = lane >> 3;
    const int jl0 = wj * 32 + jg * 4;            // local j quad (0..60)
    const int bl0 = wb * 8 + bg * 2;             // local b pair (0..14, even)
    const int j0g = r * 64 + jl0;
    const int b0g = g * 16 + bl0;

    // ---- load Whh slice (once) ----
    for (int i = tid; i < 512 * 16; i += STEP_THREADS) {
        int k = i >> 4, q = (i & 15) * 4;
        *reinterpret_cast<float4*>(ws + (size_t)k * 64 + q) =
            *reinterpret_cast<const float4*>(Whh + (size_t)k * HDIM + r * 64 + q);
    }
    __syncthreads();

    unsigned* myflag = &g_flags[(g * JCTAS + r) * 32];
    // staging map: seg = 16B of the 128B row slice; 16 rows/pass x 8 passes
    const int seg  = tid & 7;
    const int row0 = tid >> 3;

    for (int t = 0; t < TSEQ; t++) {
        const float* xpt = g_xp + (size_t)t * BATCH * HDIM;
        float4 xv0 = *reinterpret_cast<const float4*>(xpt + (size_t)b0g * HDIM + j0g);
        float4 xv1 = *reinterpret_cast<const float4*>(xpt + (size_t)(b0g + 1) * HDIM + j0g);
        ull a0 = 0ull, a1 = 0ull, a2 = 0ull, a3 = 0ull;

        if (t > 0) {
            const float2* hbase = g_ht2[(t - 1) & 1];
            const unsigned tv = (unsigned)t;

            // tid0 polls the 2 producers of chunk c; syncthreads gives the
            // whole CTA visibility (standard acquire->barrier idiom).
            auto poll = [&](int c) {
                if (tid == 0) {
                    unsigned* f0 = &g_flags[(g * JCTAS + 2 * c) * 32];
                    unsigned* f1 = &g_flags[(g * JCTAS + 2 * c + 1) * 32];
                    unsigned v0, v1;
                    for (;;) {
                        asm volatile("ld.acquire.gpu.global.u32 %0, [%1];"
                                     : "=r"(v0) : "l"(f0) : "memory");
                        asm volatile("ld.acquire.gpu.global.u32 %0, [%1];"
                                     : "=r"(v1) : "l"(f1) : "memory");
                        if (v0 >= tv && v1 >= tv) break;
                        __nanosleep(32);
                    }
                }
                __syncthreads();
            };
            auto issue = [&](int c) {
                const float2* src = hbase + (size_t)(c * 128 + row0) * BATCH
                                    + g * 16 + seg * 2;
                uint32_t dst = hs_u32 + c * HCHUNK_B + row0 * 128 + seg * 16;
                #pragma unroll
                for (int p = 0; p < 8; p++)
                    asm volatile("cp.async.cg.shared.global [%0], [%1], 16;"
                                 :: "r"(dst + p * 2048),
                                    "l"(src + (size_t)p * 16 * BATCH) : "memory");
                asm volatile("cp.async.commit_group;" ::: "memory");
            };
            auto compute = [&](int c) {
                const float* wk = ws + (size_t)(c * 128) * 64 + jl0;
                const char*  hk = hs + c * HCHUNK_B + bl0 * 8;
                #pragma unroll 8
                for (int kl = 0; kl < 128; kl++) {
                    ulonglong2 w2 = *reinterpret_cast<const ulonglong2*>(wk + (size_t)kl * 64);
                    ulonglong2 h2 = *reinterpret_cast<const ulonglong2*>(hk + (size_t)kl * 128);
                    a0 = fma2(w2.x, h2.x, a0);   // {j0,j1} @ b0
                    a1 = fma2(w2.y, h2.x, a1);   // {j2,j3} @ b0
                    a2 = fma2(w2.x, h2.y, a2);   // {j0,j1} @ b1
                    a3 = fma2(w2.y, h2.y, a3);   // {j2,j3} @ b1
                }
            };

            poll(0); issue(0);
            poll(1); issue(1);
            asm volatile("cp.async.wait_group 1;" ::: "memory");
            __syncthreads();
            poll(2); issue(2);
            compute(0);
            asm volatile("cp.async.wait_group 1;" ::: "memory");
            __syncthreads();
            poll(3); issue(3);
            compute(1);
            asm volatile("cp.async.wait_group 1;" ::: "memory");
            __syncthreads();
            compute(2);
            asm volatile("cp.async.wait_group 0;" ::: "memory");
            __syncthreads();
            compute(3);
        }

        // ---- epilogue: tanh(xp + acc) ----
        float2 p0 = upk2(a0), p1 = upk2(a1), p2 = upk2(a2), p3 = upk2(a3);
        float tb0[4] = { tanhf(xv0.x + p0.x), tanhf(xv0.y + p0.y),
                         tanhf(xv0.z + p1.x), tanhf(xv0.w + p1.y) };
        float tb1[4] = { tanhf(xv1.x + p2.x), tanhf(xv1.y + p2.y),
                         tanhf(xv1.z + p3.x), tanhf(xv1.w + p3.y) };
        float2* hout = g_ht2[t & 1];
        #pragma unroll
        for (int jj = 0; jj < 4; jj++) {
            *reinterpret_cast<float4*>(&hout[(size_t)(j0g + jj) * BATCH + b0g]) =
                make_float4(tb0[jj], tb0[jj], tb1[jj], tb1[jj]);
        }
        if (t == TSEQ - 1) {
            *reinterpret_cast<float4*>(g_hlast + (size_t)b0g * HDIM + j0g) =
                make_float4(tb0[0], tb0[1], tb0[2], tb0[3]);
            *reinterpret_cast<float4*>(g_hlast + (size_t)(b0g + 1) * HDIM + j0g) =
                make_float4(tb1[0], tb1[1], tb1[2], tb1[3]);
        }

        // ---- publish: all CTA stores done -> release flag (no atomics) ----
        __syncthreads();
        if (tid == 0)
            asm volatile("st.release.gpu.global.u32 [%0], %1;"
                         :: "l"(myflag), "r"((unsigned)(t + 1)) : "memory");
    }
}

// ============================================================================
// Kernel C: out[b][:] = softmax(h_last[b][:] @ Wph + bo).
// ============================================================================
__global__ void __launch_bounds__(128) out_softmax_kernel(
    const float* __restrict__ Wph, const float* __restrict__ bo,
    float* __restrict__ out)
{
    __shared__ float hsr[HDIM];
    __shared__ float red[128];
    int b = blockIdx.x, tid = threadIdx.x;
    for (int k = tid; k < HDIM; k += 128)
        hsr[k] = g_hlast[(size_t)b * HDIM + k];
    __syncthreads();

    int j0 = tid * 4;
    ull a0 = 0ull, a1 = 0ull;
    #pragma unroll 8
    for (int k = 0; k < HDIM; k++) {
        float4 w = *reinterpret_cast<const float4*>(Wph + (size_t)k * ODIM + j0);
        ull hv = pk2(hsr[k], hsr[k]);
        a0 = fma2(pk2(w.x, w.y), hv, a0);
        a1 = fma2(pk2(w.z, w.w), hv, a1);
    }
    float4 bv = *reinterpret_cast<const float4*>(bo + j0);
    float2 p0 = upk2(a0), p1 = upk2(a1);
    float4 v;
    v.x = p0.x + bv.x; v.y = p0.y + bv.y;
    v.z = p1.x + bv.z; v.w = p1.y + bv.w;

    float m = fmaxf(fmaxf(v.x, v.y), fmaxf(v.z, v.w));
    red[tid] = m;
    __syncthreads();
    for (int s = 64; s > 0; s >>= 1) {
        if (tid < s) red[tid] = fmaxf(red[tid], red[tid + s]);
        __syncthreads();
    }
    m = red[0];
    __syncthreads();

    v.x = expf(v.x - m); v.y = expf(v.y - m);
    v.z = expf(v.z - m); v.w = expf(v.w - m);
    red[tid] = v.x + v.y + v.z + v.w;
    __syncthreads();
    for (int s = 64; s > 0; s >>= 1) {
        if (tid < s) red[tid] += red[tid + s];
        __syncthreads();
    }
    float inv = 1.0f / red[0];
    v.x *= inv; v.y *= inv; v.z *= inv; v.w *= inv;
    *reinterpret_cast<float4*>(out + (size_t)b * ODIM + j0) = v;
}

// ============================================================================
extern "C" void kernel_launch(void* const* d_in, const int* in_sizes, int n_in,
                              void* d_out, int out_size)
{
    const float* x   = (const float*)d_in[0];
    const float* Whx = (const float*)d_in[1];
    const float* Whh = (const float*)d_in[2];
    const float* bh  = (const float*)d_in[3];
    const float* Wph = (const float*)d_in[4];
    const float* bo  = (const float*)d_in[5];
    float* out = (float*)d_out;

    cudaFuncSetAttribute(rnn_persistent,
                         cudaFuncAttributeMaxDynamicSharedMemorySize, SMEM_TOTAL);

    init_flags_kernel<<<1, 256>>>();
    xproj_kernel<<<BATCH * TSEQ / 8, 128>>>(x, Whx, bh);
    rnn_persistent<<<dim3(JCTAS, BGROUPS), STEP_THREADS, SMEM_TOTAL>>>(Whh);
    out_softmax_kernel<<<BATCH, 128>>>(Wph, bo, out);
}

// round 9
// speedup vs baseline: 1.6025x; 1.0480x over previous
#include <cuda_runtime.h>
#include <cstdint>
#include <cstddef>

#define BATCH 256
#define TSEQ  512
#define IDIM  64
#define HDIM  512
#define ODIM  512
#define JCTAS   8            // j-partition: CTA r owns j in [64r, 64r+64)
#define BGROUPS 16           // batch groups of 16 rows
#define STEP_THREADS 64

typedef unsigned long long ull;

// ---- scratch (static device allocations only) ----
__device__ float g_xp[(size_t)TSEQ * BATCH * HDIM];    // [t][b][h], 256 MiB
// hidden state, transposed plain float: g_ht[par][j*BATCH + b]
__device__ float g_ht[2][(size_t)HDIM * BATCH];        // 1 MiB
__device__ float g_hlast[(size_t)BATCH * HDIM];        // final h, [b][j]
// per-CTA step flags, one 128B line each: flag[(g*8 + r)*32]
__device__ unsigned g_flags[JCTAS * BGROUPS * 32];

// ---- packed f32x2 helpers ----
__device__ __forceinline__ ull pk2(float lo, float hi) {
    ull r; asm("mov.b64 %0, {%1,%2};" : "=l"(r) : "f"(lo), "f"(hi)); return r;
}
__device__ __forceinline__ float2 upk2(ull v) {
    float2 r; asm("mov.b64 {%0,%1}, %2;" : "=f"(r.x), "=f"(r.y) : "l"(v)); return r;
}
__device__ __forceinline__ ull fma2(ull a, ull b, ull c) {
    ull d; asm("fma.rn.f32x2 %0, %1, %2, %3;" : "=l"(d) : "l"(a), "l"(b), "l"(c)); return d;
}

// ---- smem layout ----
#define WS_BYTES   131072                 // Whh slice [512][64] floats
#define HCHUNK_B   8192                   // staged chunk: [128 k][16 b] plain float
#define SMEM_TOTAL (WS_BYTES + 4 * HCHUNK_B)   // 160 KB

// ============================================================================
__global__ void init_flags_kernel() {
    for (int i = threadIdx.x; i < JCTAS * BGROUPS * 32; i += blockDim.x)
        g_flags[i] = 0u;
}

// ============================================================================
// Kernel A: xp[t][b][:] = x[b][t][:] @ Whx + bh.  8 rows (same b) per CTA.
// ============================================================================
__global__ void __launch_bounds__(128) xproj_kernel(
    const float* __restrict__ x, const float* __restrict__ Whx,
    const float* __restrict__ bh)
{
    __shared__ float xs[8][IDIM];
    int row0 = blockIdx.x * 8;
    int b = row0 >> 9, t0 = row0 & (TSEQ - 1);
    int tid = threadIdx.x;
    for (int i = tid; i < 8 * IDIM; i += 128)
        xs[i >> 6][i & 63] = x[(size_t)(row0 + (i >> 6)) * IDIM + (i & 63)];
    __syncthreads();

    int j0 = tid * 4;
    ull a[8][2] = {};
    #pragma unroll 4
    for (int k = 0; k < IDIM; k++) {
        float4 w = *reinterpret_cast<const float4*>(Whx + (size_t)k * HDIM + j0);
        ull w01 = pk2(w.x, w.y), w23 = pk2(w.z, w.w);
        #pragma unroll
        for (int r = 0; r < 8; r++) {
            float xv = xs[r][k];
            ull x2 = pk2(xv, xv);
            a[r][0] = fma2(w01, x2, a[r][0]);
            a[r][1] = fma2(w23, x2, a[r][1]);
        }
    }
    float4 bv = *reinterpret_cast<const float4*>(bh + j0);
    #pragma unroll
    for (int r = 0; r < 8; r++) {
        float2 p0 = upk2(a[r][0]), p1 = upk2(a[r][1]);
        float4 o;
        o.x = p0.x + bv.x; o.y = p0.y + bv.y;
        o.z = p1.x + bv.z; o.w = p1.y + bv.w;
        *reinterpret_cast<float4*>(
            g_xp + ((size_t)(t0 + r) * BATCH + b) * HDIM + j0) = o;
    }
}

// ============================================================================
// Kernel B: persistent recurrence, flag-synced, crossbar-optimized.
// Grid (8 j, 16 b) = 128 CTAs x 64 thr (single wave, 160KB smem, 1 CTA/SM).
// Thread (jt 0..15, bt 0..3): tile 4j x 4b -> 16 MACs per 32 delivered bytes.
// Per kl: LDS.128 W (4j plain) + LDS.128 h (4b plain) + 4 reg-splats + 8 FFMA2.
// Accumulators a[b][jp] pack j-pairs; h splats {hb,hb} formed in registers.
// Sync structure identical to R7 (proven): per-producer flags, tid0 poll,
// 4-chunk cp.async pipeline (chunk c depends on producers 2c, 2c+1).
// ============================================================================
__global__ void __launch_bounds__(STEP_THREADS, 1) rnn_persistent(
    const float* __restrict__ Whh)
{
    extern __shared__ char sm[];
    float* ws = reinterpret_cast<float*>(sm);                    // [512][64]
    float* hs = reinterpret_cast<float*>(sm + WS_BYTES);         // 4 x [128][16]
    uint32_t hs_u32 = (uint32_t)__cvta_generic_to_shared(hs);

    const int r = blockIdx.x;          // 0..7  (j slice)
    const int g = blockIdx.y;          // 0..15 (batch group)
    const int tid = threadIdx.x;
    const int jt = tid & 15;           // 16 j-quads
    const int bt = tid >> 4;           // 4 b-quads
    const int jl0 = jt * 4;
    const int j0g = r * 64 + jl0;
    const int b0g = g * 16 + bt * 4;

    // ---- load Whh slice [512][64] (once) ----
    for (int i = tid; i < 512 * 16; i += STEP_THREADS) {
        int k = i >> 4, q = (i & 15) * 4;
        *reinterpret_cast<float4*>(ws + (size_t)k * 64 + q) =
            *reinterpret_cast<const float4*>(Whh + (size_t)k * HDIM + r * 64 + q);
    }
    __syncthreads();

    unsigned* myflag = &g_flags[(g * JCTAS + r) * 32];
    // staging map: chunk = [128 k][16 b] floats, 64B rows; 4 segs/row,
    // 16 rows per pass, 8 passes. seg = tid&3, row0 = tid>>2 (0..15).
    const int seg  = tid & 3;
    const int row0 = tid >> 2;

    for (int t = 0; t < TSEQ; t++) {
        const float* xpt = g_xp + (size_t)t * BATCH * HDIM;
        float4 xv[4];
        #pragma unroll
        for (int bb = 0; bb < 4; bb++)
            xv[bb] = *reinterpret_cast<const float4*>(
                xpt + (size_t)(b0g + bb) * HDIM + j0g);
        ull a[4][2] = {};    // [b][j-pair]: {j0,j1}, {j2,j3}

        if (t > 0) {
            const float* hbase = g_ht[(t - 1) & 1];
            const unsigned tv = (unsigned)t;

            auto poll = [&](int c) {
                if (tid == 0) {
                    unsigned* f0 = &g_flags[(g * JCTAS + 2 * c) * 32];
                    unsigned* f1 = &g_flags[(g * JCTAS + 2 * c + 1) * 32];
                    unsigned v0, v1;
                    for (;;) {
                        asm volatile("ld.acquire.gpu.global.u32 %0, [%1];"
                                     : "=r"(v0) : "l"(f0) : "memory");
                        asm volatile("ld.acquire.gpu.global.u32 %0, [%1];"
                                     : "=r"(v1) : "l"(f1) : "memory");
                        if (v0 >= tv && v1 >= tv) break;
                        __nanosleep(32);
                    }
                }
                __syncthreads();
            };
            auto issue = [&](int c) {
                const float* src = hbase + (size_t)(c * 128 + row0) * BATCH
                                   + g * 16 + seg * 4;
                uint32_t dst = hs_u32 + c * HCHUNK_B + row0 * 64 + seg * 16;
                #pragma unroll
                for (int p = 0; p < 8; p++)
                    asm volatile("cp.async.cg.shared.global [%0], [%1], 16;"
                                 :: "r"(dst + p * 1024),
                                    "l"(src + (size_t)p * 16 * BATCH) : "memory");
                asm volatile("cp.async.commit_group;" ::: "memory");
            };
            auto compute = [&](int c) {
                const float* wk = ws + (size_t)(c * 128) * 64 + jl0;
                const float* hk = hs + (size_t)c * 2048 + bt * 4;
                #pragma unroll 8
                for (int kl = 0; kl < 128; kl++) {
                    float4 w4 = *reinterpret_cast<const float4*>(wk + (size_t)kl * 64);
                    float4 h4 = *reinterpret_cast<const float4*>(hk + (size_t)kl * 16);
                    ull w01 = pk2(w4.x, w4.y), w23 = pk2(w4.z, w4.w);  // aligned pairs
                    ull s0 = pk2(h4.x, h4.x);
                    ull s1 = pk2(h4.y, h4.y);
                    ull s2 = pk2(h4.z, h4.z);
                    ull s3 = pk2(h4.w, h4.w);
                    a[0][0] = fma2(w01, s0, a[0][0]);
                    a[0][1] = fma2(w23, s0, a[0][1]);
                    a[1][0] = fma2(w01, s1, a[1][0]);
                    a[1][1] = fma2(w23, s1, a[1][1]);
                    a[2][0] = fma2(w01, s2, a[2][0]);
                    a[2][1] = fma2(w23, s2, a[2][1]);
                    a[3][0] = fma2(w01, s3, a[3][0]);
                    a[3][1] = fma2(w23, s3, a[3][1]);
                }
            };

            poll(0); issue(0);
            poll(1); issue(1);
            asm volatile("cp.async.wait_group 1;" ::: "memory");
            __syncthreads();
            poll(2); issue(2);
            compute(0);
            asm volatile("cp.async.wait_group 1;" ::: "memory");
            __syncthreads();
            poll(3); issue(3);
            compute(1);
            asm volatile("cp.async.wait_group 1;" ::: "memory");
            __syncthreads();
            compute(2);
            asm volatile("cp.async.wait_group 0;" ::: "memory");
            __syncthreads();
            compute(3);
        }

        // ---- epilogue: o[b][j] = tanh(xp + acc) ----
        float o[4][4];
        #pragma unroll
        for (int bb = 0; bb < 4; bb++) {
            float2 p0 = upk2(a[bb][0]), p1 = upk2(a[bb][1]);
            o[bb][0] = tanhf(xv[bb].x + p0.x);
            o[bb][1] = tanhf(xv[bb].y + p0.y);
            o[bb][2] = tanhf(xv[bb].z + p1.x);
            o[bb][3] = tanhf(xv[bb].w + p1.y);
        }
        // transposed store h[j][b] (plain float4 over b)
        float* hout = g_ht[t & 1];
        #pragma unroll
        for (int jj = 0; jj < 4; jj++)
            *reinterpret_cast<float4*>(hout + (size_t)(j0g + jj) * BATCH + b0g) =
                make_float4(o[0][jj], o[1][jj], o[2][jj], o[3][jj]);
        if (t == TSEQ - 1) {
            #pragma unroll
            for (int bb = 0; bb < 4; bb++)
                *reinterpret_cast<float4*>(g_hlast + (size_t)(b0g + bb) * HDIM + j0g) =
                    make_float4(o[bb][0], o[bb][1], o[bb][2], o[bb][3]);
        }

        // ---- publish (no atomics) ----
        __syncthreads();
        if (tid == 0)
            asm volatile("st.release.gpu.global.u32 [%0], %1;"
                         :: "l"(myflag), "r"((unsigned)(t + 1)) : "memory");
    }
}

// ============================================================================
// Kernel C: out[b][:] = softmax(h_last[b][:] @ Wph + bo).
// ============================================================================
__global__ void __launch_bounds__(128) out_softmax_kernel(
    const float* __restrict__ Wph, const float* __restrict__ bo,
    float* __restrict__ out)
{
    __shared__ float hsr[HDIM];
    __shared__ float red[128];
    int b = blockIdx.x, tid = threadIdx.x;
    for (int k = tid; k < HDIM; k += 128)
        hsr[k] = g_hlast[(size_t)b * HDIM + k];
    __syncthreads();

    int j0 = tid * 4;
    ull a0 = 0ull, a1 = 0ull;
    #pragma unroll 8
    for (int k = 0; k < HDIM; k++) {
        float4 w = *reinterpret_cast<const float4*>(Wph + (size_t)k * ODIM + j0);
        ull hv = pk2(hsr[k], hsr[k]);
        a0 = fma2(pk2(w.x, w.y), hv, a0);
        a1 = fma2(pk2(w.z, w.w), hv, a1);
    }
    float4 bv = *reinterpret_cast<const float4*>(bo + j0);
    float2 p0 = upk2(a0), p1 = upk2(a1);
    float4 v;
    v.x = p0.x + bv.x; v.y = p0.y + bv.y;
    v.z = p1.x + bv.z; v.w = p1.y + bv.w;

    float m = fmaxf(fmaxf(v.x, v.y), fmaxf(v.z, v.w));
    red[tid] = m;
    __syncthreads();
    for (int s = 64; s > 0; s >>= 1) {
        if (tid < s) red[tid] = fmaxf(red[tid], red[tid + s]);
        __syncthreads();
    }
    m = red[0];
    __syncthreads();

    v.x = expf(v.x - m); v.y = expf(v.y - m);
    v.z = expf(v.z - m); v.w = expf(v.w - m);
    red[tid] = v.x + v.y + v.z + v.w;
    __syncthreads();
    for (int s = 64; s > 0; s >>= 1) {
        if (tid < s) red[tid] += red[tid + s];
        __syncthreads();
    }
    float inv = 1.0f / red[0];
    v.x *= inv; v.y *= inv; v.z *= inv; v.w *= inv;
    *reinterpret_cast<float4*>(out + (size_t)b * ODIM + j0) = v;
}

// ============================================================================
extern "C" void kernel_launch(void* const* d_in, const int* in_sizes, int n_in,
                              void* d_out, int out_size)
{
    const float* x   = (const float*)d_in[0];
    const float* Whx = (const float*)d_in[1];
    const float* Whh = (const float*)d_in[2];
    const float* bh  = (const float*)d_in[3];
    const float* Wph = (const float*)d_in[4];
    const float* bo  = (const float*)d_in[5];
    float* out = (float*)d_out;

    cudaFuncSetAttribute(rnn_persistent,
                         cudaFuncAttributeMaxDynamicSharedMemorySize, SMEM_TOTAL);

    init_flags_kernel<<<1, 256>>>();
    xproj_kernel<<<BATCH * TSEQ / 8, 128>>>(x, Whx, bh);
    rnn_persistent<<<dim3(JCTAS, BGROUPS), STEP_THREADS, SMEM_TOTAL>>>(Whh);
    out_softmax_kernel<<<BATCH, 128>>>(Wph, bo, out);
}